// round 7
// baseline (speedup 1.0000x reference)
#include <cuda_runtime.h>
#include <math.h>
#include <stdint.h>

#define LDIM 512
#define BDIM 64
#define CDIM 512
#define RANKS 8
#define COLS 64           // E-columns per CTA
#define GRPB 4            // batches per group
#define NGRP 2            // groups (independent recursions) per cluster

__device__ float g_logz[BDIM];
__device__ float g_scorep[BDIM];

// ---------------------------------------------------------------------------
__device__ __forceinline__ unsigned smem_u32(const void* p) {
    return (unsigned)__cvta_generic_to_shared(p);
}
__device__ __forceinline__ unsigned mapa_rank(unsigned saddr, unsigned rank) {
    unsigned r;
    asm("mapa.shared::cluster.u32 %0, %1, %2;" : "=r"(r) : "r"(saddr), "r"(rank));
    return r;
}
__device__ __forceinline__ void stc_f32(unsigned saddr, float v) {
    asm volatile("st.shared::cluster.f32 [%0], %1;" :: "r"(saddr), "f"(v) : "memory");
}
__device__ __forceinline__ void stc_v4(unsigned saddr, float4 v) {
    asm volatile("st.shared::cluster.v4.f32 [%0], {%1,%2,%3,%4};"
                 :: "r"(saddr), "f"(v.x), "f"(v.y), "f"(v.z), "f"(v.w) : "memory");
}
__device__ __forceinline__ void cluster_sync_() {
    asm volatile("barrier.cluster.arrive.aligned;" ::: "memory");
    asm volatile("barrier.cluster.wait.aligned;"   ::: "memory");
}
__device__ __forceinline__ unsigned long long ffma2(unsigned long long a,
                                                    unsigned long long b,
                                                    unsigned long long c) {
    unsigned long long d;
    asm("fma.rn.f32x2 %0, %1, %2, %3;" : "=l"(d) : "l"(a), "l"(b), "l"(c));
    return d;
}
__device__ __forceinline__ unsigned long long dup2(float v) {
    unsigned long long r; unsigned u = __float_as_uint(v);
    asm("mov.b64 %0, {%1, %1};" : "=l"(r) : "r"(u));
    return r;
}
__device__ __forceinline__ float2 unpk(unsigned long long v) {
    unsigned a, b;
    asm("mov.b64 {%0, %1}, %2;" : "=r"(a), "=r"(b) : "l"(v));
    return make_float2(__uint_as_float(a), __uint_as_float(b));
}
__device__ __forceinline__ void mbar_init(unsigned addr, unsigned cnt) {
    asm volatile("mbarrier.init.shared.b64 [%0], %1;" :: "r"(addr), "r"(cnt) : "memory");
}
__device__ __forceinline__ void mbar_arrive_remote(unsigned addr) {
    asm volatile("mbarrier.arrive.release.cluster.shared::cluster.b64 _, [%0];"
                 :: "r"(addr) : "memory");
}
__device__ __forceinline__ void mbar_wait_acq(unsigned addr, unsigned parity) {
    unsigned done;
    asm volatile(
        "{\n\t.reg .pred p;\n\t"
        "mbarrier.try_wait.parity.acquire.cluster.shared::cta.b64 p, [%1], %2;\n\t"
        "selp.b32 %0, 1, 0, p;\n\t}"
        : "=r"(done) : "r"(addr), "r"(parity) : "memory");
    if (!done) {
        asm volatile(
            "{\n\t.reg .pred P1;\n\t"
            "WL_%=:\n\t"
            "mbarrier.try_wait.parity.acquire.cluster.shared::cta.b64 P1, [%0], %1, 0x989680;\n\t"
            "@P1 bra.uni WD_%=;\n\t"
            "bra.uni WL_%=;\n\t"
            "WD_%=:\n\t}"
            :: "r"(addr), "r"(parity) : "memory");
    }
}
__device__ __forceinline__ int mask_byte_probe(const unsigned char* m8) {
    int allnz = 1;
    for (int b = 0; b < BDIM; b++) if (m8[b] == 0) allnz = 0;
    return allnz;
}
__device__ __forceinline__ int get_mask2(const void* mask, int idx, int isbyte) {
    if (isbyte) return ((const unsigned char*)mask)[idx] != 0;
    return ((const int*)mask)[idx] != 0;
}

// ---------------------------------------------------------------------------
struct __align__(16) SM {
    float E[CDIM * COLS];                 // 128 KB
    float pbuf[NGRP][2][CDIM][GRPB];      // 32 KB   assembled p per group/parity
    float part[32][GRPB][COLS];           // 32 KB   matvec partials (shared A/B)
    float stage[NGRP][COLS][GRPB];        // 2 KB
    float pmail[NGRP][2][RANKS][GRPB];    // 1 KB    lagged local maxes
    float wred[NGRP][8];
    float wsum[NGRP][8];
    float fm[RANKS][8], fs[RANKS][8];
    unsigned long long mbar[NGRP][2];
    unsigned char act[NGRP][LDIM][GRPB];
    unsigned char anyg[NGRP][LDIM];
    int isbyte;
};

// one pipeline step of one group: wait -> matvec -> combine
__device__ __forceinline__ void step_group(
    SM* sm, int grp, int par, int ph, int i,
    int t, int g, int col, int lane, int wrp, int cg, int seg,
    float e_reg, float& a, float& m_used)
{
    mbar_wait_acq(smem_u32(&sm->mbar[grp][par]), (unsigned)ph);

    // matvec on SMEM E slice (4 batches per E element)
    {
        const ulonglong2* Ev = (const ulonglong2*)sm->E + seg * 16 * (COLS / 4) + cg;
        const float4*     pv = (const float4*)&sm->pbuf[grp][par][seg * 16][0];
        unsigned long long ac[8];
        #pragma unroll
        for (int k = 0; k < 8; k++) ac[k] = 0ull;
        #pragma unroll
        for (int c = 0; c < 16; c++) {
            ulonglong2 e  = Ev[c * (COLS / 4)];
            float4     pq = pv[c];
            unsigned long long d0 = dup2(pq.x), d1 = dup2(pq.y),
                               d2 = dup2(pq.z), d3 = dup2(pq.w);
            ac[0] = ffma2(d0, e.x, ac[0]); ac[1] = ffma2(d0, e.y, ac[1]);
            ac[2] = ffma2(d1, e.x, ac[2]); ac[3] = ffma2(d1, e.y, ac[3]);
            ac[4] = ffma2(d2, e.x, ac[4]); ac[5] = ffma2(d2, e.y, ac[5]);
            ac[6] = ffma2(d3, e.x, ac[6]); ac[7] = ffma2(d3, e.y, ac[7]);
        }
        #pragma unroll
        for (int gg = 0; gg < GRPB; gg++) {
            float2 lo = unpk(ac[2 * gg]), hi = unpk(ac[2 * gg + 1]);
            *(float4*)&sm->part[seg][gg][cg * 4] = make_float4(lo.x, lo.y, hi.x, hi.y);
        }
    }
    __syncthreads();

    if (t < 256) {
        float s = 0.f;
        #pragma unroll
        for (int r = 0; r < RANKS; r++)
            s += (sm->part[4 * r][g][col]     + sm->part[4 * r + 1][g][col])
               + (sm->part[4 * r + 2][g][col] + sm->part[4 * r + 3][g][col]);
        float m_next = sm->pmail[grp][par][0][g];
        #pragma unroll
        for (int r = 1; r < RANKS; r++) m_next = fmaxf(m_next, sm->pmail[grp][par][r][g]);
        float anew = m_used + __logf(s) + e_reg;
        if (sm->act[grp][i][g]) a = anew;
        m_used = m_next;
        sm->stage[grp][col][g] = __expf(a - m_next);
        float m = a;
        #pragma unroll
        for (int o = 16; o; o >>= 1) m = fmaxf(m, __shfl_xor_sync(0xffffffffu, m, o));
        if (lane == 0) sm->wred[grp][wrp] = m;
    }
    __syncthreads();
}

__global__ void __cluster_dims__(RANKS, 1, 1) __launch_bounds__(512, 1)
forward_kernel(const float* __restrict__ emit,
               const void*  __restrict__ mask,
               const float* __restrict__ trans,
               const float* __restrict__ tfs,
               const float* __restrict__ tte)
{
    extern __shared__ char smraw[];
    SM* sm = (SM*)smraw;

    const int t    = threadIdx.x;
    const int cta  = blockIdx.x;
    const int rank = cta & (RANKS - 1);
    const int cl   = cta >> 3;            // cluster id (0..7), 8 batches each

    const int g    = (t >> 6) & 3;
    const int col  = t & 63;
    const int cg_glob = rank * COLS + col;
    const int lane = t & 31;
    const int wrp  = t >> 5;
    const int cg   = t & 15;
    const int seg  = t >> 4;

    const int bA = cl * 8 + g;
    const int bB = cl * 8 + 4 + g;

    if (t == 0) {
        sm->isbyte = mask_byte_probe((const unsigned char*)mask);
        mbar_init(smem_u32(&sm->mbar[0][0]), RANKS);
        mbar_init(smem_u32(&sm->mbar[0][1]), RANKS);
        mbar_init(smem_u32(&sm->mbar[1][0]), RANKS);
        mbar_init(smem_u32(&sm->mbar[1][1]), RANKS);
    }

    // E slice = exp(trans[:, rank*64 .. +64])
    for (int idx = t; idx < CDIM * COLS; idx += 512) {
        int row = idx >> 6, c = idx & 63;
        sm->E[idx] = expf(trans[(size_t)row * CDIM + rank * COLS + c]);
    }
    __syncthreads();

    // mask flags for both groups
    const int isbyte = sm->isbyte;
    {
        int i = t;  // one i per thread (LDIM == 512 == blockDim)
        #pragma unroll
        for (int grp = 0; grp < NGRP; grp++) {
            int anyv = 0;
            #pragma unroll
            for (int gg = 0; gg < GRPB; gg++) {
                int m = get_mask2(mask, i * BDIM + cl * 8 + grp * 4 + gg, isbyte);
                sm->act[grp][i][gg] = (unsigned char)m;
                anyv |= m;
            }
            sm->anyg[grp][i] = (unsigned char)anyv;
        }
    }

    // alpha_0 for both groups + warp maxes
    float aA = 0.f, aB = 0.f, mA = 0.f, mB = 0.f;
    if (t < 256) {
        aA = emit[(size_t)bA * CDIM + cg_glob] + tfs[cg_glob];
        aB = emit[(size_t)bB * CDIM + cg_glob] + tfs[cg_glob];
        float m0 = aA, m1 = aB;
        #pragma unroll
        for (int o = 16; o; o >>= 1) {
            m0 = fmaxf(m0, __shfl_xor_sync(0xffffffffu, m0, o));
            m1 = fmaxf(m1, __shfl_xor_sync(0xffffffffu, m1, o));
        }
        if (lane == 0) { sm->wred[0][wrp] = m0; sm->wred[1][wrp] = m1; }
    }
    __syncthreads();

    // prologue: exchange alpha_0 local maxes (covers mbar-init visibility too)
    if (t < 64) {
        int dr = t >> 3, q = t & 7;
        float ml = fmaxf(sm->wred[q >> 2][2 * (q & 3)], sm->wred[q >> 2][2 * (q & 3) + 1]);
        stc_f32(mapa_rank(smem_u32(&sm->fm[0][0]), dr) + (unsigned)((rank * 8 + q) * 4), ml);
    }
    cluster_sync_();
    if (t < 256) {
        float ga = sm->fm[0][g], gb = sm->fm[0][4 + g];
        #pragma unroll
        for (int r = 1; r < RANKS; r++) {
            ga = fmaxf(ga, sm->fm[r][g]);
            gb = fmaxf(gb, sm->fm[r][4 + g]);
        }
        mA = ga; mB = gb;
        sm->stage[0][col][g] = __expf(aA - mA);
        sm->stage[1][col][g] = __expf(aB - mB);
    }
    __syncthreads();

    // push targets: warp wrp ships to rank wrp
    unsigned p_dst = 0, m_dst = 0, b_dst = 0;
    if (wrp < 8) {
        p_dst = mapa_rank(smem_u32(&sm->pbuf[0][0][0][0]), wrp);
        m_dst = mapa_rank(smem_u32(&sm->pmail[0][0][0][0]), wrp);
        b_dst = mapa_rank(smem_u32(&sm->mbar[0][0]), wrp);
    }

    int usesA = 0, usesB = 0;
    for (int i = 1; i < LDIM; i++) {
        const int doA = sm->anyg[0][i], doB = sm->anyg[1][i];
        if (!(doA | doB)) continue;
        const int parA = usesA & 1, parB = usesB & 1;

        float eA = 0.f, eB = 0.f;
        if (t < 256) {
            if (doA) eA = emit[((size_t)i * BDIM + bA) * CDIM + cg_glob];
            if (doB) eB = emit[((size_t)i * BDIM + bB) * CDIM + cg_glob];
            if (doA) {
                const float4* s4 = (const float4*)&sm->stage[0][0][0];
                float4 v0 = s4[lane * 2], v1 = s4[lane * 2 + 1];
                unsigned off = (unsigned)((parA * CDIM + rank * COLS) * GRPB * 4);
                stc_v4(p_dst + off + (unsigned)(lane * 32),      v0);
                stc_v4(p_dst + off + (unsigned)(lane * 32 + 16), v1);
                if (lane == 0) {
                    float4 mv = make_float4(fmaxf(sm->wred[0][0], sm->wred[0][1]),
                                            fmaxf(sm->wred[0][2], sm->wred[0][3]),
                                            fmaxf(sm->wred[0][4], sm->wred[0][5]),
                                            fmaxf(sm->wred[0][6], sm->wred[0][7]));
                    stc_v4(m_dst + (unsigned)((parA * RANKS + rank) * 16), mv);
                }
            }
            if (doB) {
                const float4* s4 = (const float4*)&sm->stage[1][0][0];
                float4 v0 = s4[lane * 2], v1 = s4[lane * 2 + 1];
                unsigned off = (unsigned)(((2 + parB) * CDIM + rank * COLS) * GRPB * 4);
                stc_v4(p_dst + off + (unsigned)(lane * 32),      v0);
                stc_v4(p_dst + off + (unsigned)(lane * 32 + 16), v1);
                if (lane == 0) {
                    float4 mv = make_float4(fmaxf(sm->wred[1][0], sm->wred[1][1]),
                                            fmaxf(sm->wred[1][2], sm->wred[1][3]),
                                            fmaxf(sm->wred[1][4], sm->wred[1][5]),
                                            fmaxf(sm->wred[1][6], sm->wred[1][7]));
                    stc_v4(m_dst + (unsigned)(((2 + parB) * RANKS + rank) * 16), mv);
                }
            }
            __syncwarp();
            if (lane == 0) {
                if (doA) mbar_arrive_remote(b_dst + (unsigned)(parA * 8));
                if (doB) mbar_arrive_remote(b_dst + (unsigned)((2 + parB) * 8));
            }
        }

        if (doA) { step_group(sm, 0, parA, (usesA >> 1) & 1, i, t, g, col, lane, wrp, cg, seg, eA, aA, mA); usesA++; }
        if (doB) { step_group(sm, 1, parB, (usesB >> 1) & 1, i, t, g, col, lane, wrp, cg, seg, eB, aB, mB); usesB++; }
    }

    // ---- final: log_z for 8 batches across 8 ranks ----
    if (t < 256) {
        float vA = aA + tte[cg_glob];
        float vB = aB + tte[cg_glob];
        float m0 = vA, m1 = vB;
        #pragma unroll
        for (int o = 16; o; o >>= 1) {
            m0 = fmaxf(m0, __shfl_xor_sync(0xffffffffu, m0, o));
            m1 = fmaxf(m1, __shfl_xor_sync(0xffffffffu, m1, o));
        }
        if (lane == 0) { sm->wred[0][wrp] = m0; sm->wred[1][wrp] = m1; }
        __syncwarp();
        // need block-level maxes; barrier below
        sm->stage[0][col][g] = vA;   // stash v for after barrier
        sm->stage[1][col][g] = vB;
    }
    __syncthreads();
    if (t < 256) {
        float mlA = fmaxf(sm->wred[0][2 * g], sm->wred[0][2 * g + 1]);
        float mlB = fmaxf(sm->wred[1][2 * g], sm->wred[1][2 * g + 1]);
        float e0 = expf(sm->stage[0][col][g] - mlA);
        float e1 = expf(sm->stage[1][col][g] - mlB);
        #pragma unroll
        for (int o = 16; o; o >>= 1) {
            e0 += __shfl_xor_sync(0xffffffffu, e0, o);
            e1 += __shfl_xor_sync(0xffffffffu, e1, o);
        }
        if (lane == 0) { sm->wsum[0][wrp] = e0; sm->wsum[1][wrp] = e1; }
    }
    __syncthreads();
    if (t < 8) {
        int grp = t >> 2, g2 = t & 3;
        float ml = fmaxf(sm->wred[grp][2 * g2], sm->wred[grp][2 * g2 + 1]);
        float sl = sm->wsum[grp][2 * g2] + sm->wsum[grp][2 * g2 + 1];
        unsigned fm0 = mapa_rank(smem_u32(&sm->fm[0][0]), 0);
        unsigned fs0 = mapa_rank(smem_u32(&sm->fs[0][0]), 0);
        stc_f32(fm0 + (unsigned)((rank * 8 + t) * 4), ml);
        stc_f32(fs0 + (unsigned)((rank * 8 + t) * 4), sl);
    }
    cluster_sync_();
    if (rank == 0 && t < 8) {
        float mg = sm->fm[0][t];
        #pragma unroll
        for (int r = 1; r < RANKS; r++) mg = fmaxf(mg, sm->fm[r][t]);
        float tot = 0.f;
        #pragma unroll
        for (int r = 0; r < RANKS; r++) tot += sm->fs[r][t] * expf(sm->fm[r][t] - mg);
        g_logz[cl * 8 + t] = mg + logf(tot);
    }
}

// ---------------------------------------------------------------------------
__global__ __launch_bounds__(512) void score_kernel(
    const float* __restrict__ emit,
    const int*   __restrict__ target,
    const void*  __restrict__ mask,
    const float* __restrict__ trans,
    const float* __restrict__ tfs,
    const float* __restrict__ tte)
{
    __shared__ int s_isbyte;
    __shared__ float red[16];
    const int t = threadIdx.x, warp = t >> 5, lane = t & 31;
    if (t == 0) s_isbyte = mask_byte_probe((const unsigned char*)mask);
    __syncthreads();
    const int isbyte = s_isbyte;

    const int idx = blockIdx.x * 512 + t;
    const int i = idx >> 6;
    const int b = idx & 63;

    float contrib = 0.f;
    if (get_mask2(mask, i * BDIM + b, isbyte)) {
        int ti = target[i * BDIM + b];
        contrib = emit[((size_t)i * BDIM + b) * CDIM + ti];
        if (i > 0) {
            int tp = target[(i - 1) * BDIM + b];
            contrib += trans[(size_t)tp * CDIM + ti];
        } else {
            contrib += tfs[ti];
        }
        int nxt = (i + 1 < LDIM) ? get_mask2(mask, (i + 1) * BDIM + b, isbyte) : 0;
        if (!nxt) contrib += tte[ti];
    }
    #pragma unroll
    for (int o = 16; o; o >>= 1) contrib += __shfl_xor_sync(0xffffffffu, contrib, o);
    if (lane == 0) red[warp] = contrib;
    __syncthreads();
    if (t == 0) {
        float s = 0.f;
        #pragma unroll
        for (int w = 0; w < 16; w++) s += red[w];
        g_scorep[blockIdx.x] = s;
    }
}

// ---------------------------------------------------------------------------
__global__ void finalize_kernel(float* __restrict__ out) {
    __shared__ float red[2];
    const int t = threadIdx.x, lane = t & 31, warp = t >> 5;
    float v = (t < BDIM) ? (g_logz[t] - g_scorep[t]) : 0.f;
    #pragma unroll
    for (int o = 16; o; o >>= 1) v += __shfl_xor_sync(0xffffffffu, v, o);
    if (lane == 0) red[warp] = v;
    __syncthreads();
    if (t == 0) out[0] = (red[0] + red[1]) / (float)BDIM;
}

// ---------------------------------------------------------------------------
extern "C" void kernel_launch(void* const* d_in, const int* in_sizes, int n_in,
                              void* d_out, int out_size) {
    const float* emit   = (const float*)d_in[0];
    const int*   target = (const int*)  d_in[1];
    const void*  mask   =               d_in[2];
    const float* trans  = (const float*)d_in[3];
    const float* tfs    = (const float*)d_in[4];
    const float* tte    = (const float*)d_in[5];
    float* out = (float*)d_out;

    cudaFuncSetAttribute(forward_kernel,
                         cudaFuncAttributeMaxDynamicSharedMemorySize, (int)sizeof(SM));

    forward_kernel<<<8 * RANKS, 512, sizeof(SM)>>>(emit, mask, trans, tfs, tte);
    score_kernel<<<64, 512>>>(emit, target, mask, trans, tfs, tte);
    finalize_kernel<<<1, 64>>>(out);
}

// round 8
// speedup vs baseline: 1.0024x; 1.0024x over previous
#include <cuda_runtime.h>
#include <math.h>
#include <stdint.h>

#define LDIM 512
#define BDIM 64
#define CDIM 512
#define RANKS 8
#define COLS 64           // E-columns per CTA
#define GRPB 4            // batches per group
#define NGRP 2            // groups (independent recursions) per cluster

__device__ float g_logz[BDIM];
__device__ float g_scorep[BDIM];

// ---------------------------------------------------------------------------
__device__ __forceinline__ unsigned smem_u32(const void* p) {
    return (unsigned)__cvta_generic_to_shared(p);
}
__device__ __forceinline__ unsigned mapa_rank(unsigned saddr, unsigned rank) {
    unsigned r;
    asm("mapa.shared::cluster.u32 %0, %1, %2;" : "=r"(r) : "r"(saddr), "r"(rank));
    return r;
}
__device__ __forceinline__ void stc_f32(unsigned saddr, float v) {
    asm volatile("st.shared::cluster.f32 [%0], %1;" :: "r"(saddr), "f"(v) : "memory");
}
__device__ __forceinline__ void stc_v4(unsigned saddr, float4 v) {
    asm volatile("st.shared::cluster.v4.f32 [%0], {%1,%2,%3,%4};"
                 :: "r"(saddr), "f"(v.x), "f"(v.y), "f"(v.z), "f"(v.w) : "memory");
}
__device__ __forceinline__ void cluster_sync_() {
    asm volatile("barrier.cluster.arrive.aligned;" ::: "memory");
    asm volatile("barrier.cluster.wait.aligned;"   ::: "memory");
}
__device__ __forceinline__ unsigned long long ffma2(unsigned long long a,
                                                    unsigned long long b,
                                                    unsigned long long c) {
    unsigned long long d;
    asm("fma.rn.f32x2 %0, %1, %2, %3;" : "=l"(d) : "l"(a), "l"(b), "l"(c));
    return d;
}
__device__ __forceinline__ unsigned long long dup2(float v) {
    unsigned long long r; unsigned u = __float_as_uint(v);
    asm("mov.b64 %0, {%1, %1};" : "=l"(r) : "r"(u));
    return r;
}
__device__ __forceinline__ float2 unpk(unsigned long long v) {
    unsigned a, b;
    asm("mov.b64 {%0, %1}, %2;" : "=r"(a), "=r"(b) : "l"(v));
    return make_float2(__uint_as_float(a), __uint_as_float(b));
}
__device__ __forceinline__ void mbar_init(unsigned addr, unsigned cnt) {
    asm volatile("mbarrier.init.shared.b64 [%0], %1;" :: "r"(addr), "r"(cnt) : "memory");
}
__device__ __forceinline__ void mbar_arrive_remote(unsigned addr) {
    asm volatile("mbarrier.arrive.release.cluster.shared::cluster.b64 _, [%0];"
                 :: "r"(addr) : "memory");
}
__device__ __forceinline__ void mbar_wait_acq(unsigned addr, unsigned parity) {
    unsigned done;
    asm volatile(
        "{\n\t.reg .pred p;\n\t"
        "mbarrier.try_wait.parity.acquire.cluster.shared::cta.b64 p, [%1], %2;\n\t"
        "selp.b32 %0, 1, 0, p;\n\t}"
        : "=r"(done) : "r"(addr), "r"(parity) : "memory");
    if (!done) {
        asm volatile(
            "{\n\t.reg .pred P1;\n\t"
            "WL_%=:\n\t"
            "mbarrier.try_wait.parity.acquire.cluster.shared::cta.b64 P1, [%0], %1, 0x989680;\n\t"
            "@P1 bra.uni WD_%=;\n\t"
            "bra.uni WL_%=;\n\t"
            "WD_%=:\n\t}"
            :: "r"(addr), "r"(parity) : "memory");
    }
}
__device__ __forceinline__ int mask_byte_probe(const unsigned char* m8) {
    int allnz = 1;
    for (int b = 0; b < BDIM; b++) if (m8[b] == 0) allnz = 0;
    return allnz;
}
__device__ __forceinline__ int get_mask2(const void* mask, int idx, int isbyte) {
    if (isbyte) return ((const unsigned char*)mask)[idx] != 0;
    return ((const int*)mask)[idx] != 0;
}

// ---------------------------------------------------------------------------
struct __align__(16) SM {
    float E[CDIM * COLS];                 // 128 KB
    float pbuf[NGRP][2][CDIM][GRPB];      // 32 KB   assembled p per group/parity
    float part[32][GRPB][COLS];           // 32 KB   matvec partials (shared A/B)
    float stage[NGRP][COLS][GRPB];        // 2 KB
    float pmail[NGRP][2][RANKS][GRPB];    // 1 KB    lagged local maxes
    float wred[NGRP][8];
    float wsum[NGRP][8];
    float fm[RANKS][8], fs[RANKS][8];
    unsigned long long mbar[NGRP][2];
    unsigned char act[NGRP][LDIM][GRPB];
    unsigned char anyg[NGRP][LDIM];
    int isbyte;
};

// one pipeline step of one group: wait -> matvec -> combine
__device__ __forceinline__ void step_group(
    SM* sm, int grp, int par, int ph, int i,
    int t, int g, int col, int lane, int wrp, int cg, int seg,
    float e_reg, float& a, float& m_used)
{
    mbar_wait_acq(smem_u32(&sm->mbar[grp][par]), (unsigned)ph);

    // matvec on SMEM E slice (4 batches per E element)
    {
        const ulonglong2* Ev = (const ulonglong2*)sm->E + seg * 16 * (COLS / 4) + cg;
        const float4*     pv = (const float4*)&sm->pbuf[grp][par][seg * 16][0];
        unsigned long long ac[8];
        #pragma unroll
        for (int k = 0; k < 8; k++) ac[k] = 0ull;
        #pragma unroll
        for (int c = 0; c < 16; c++) {
            ulonglong2 e  = Ev[c * (COLS / 4)];
            float4     pq = pv[c];
            unsigned long long d0 = dup2(pq.x), d1 = dup2(pq.y),
                               d2 = dup2(pq.z), d3 = dup2(pq.w);
            ac[0] = ffma2(d0, e.x, ac[0]); ac[1] = ffma2(d0, e.y, ac[1]);
            ac[2] = ffma2(d1, e.x, ac[2]); ac[3] = ffma2(d1, e.y, ac[3]);
            ac[4] = ffma2(d2, e.x, ac[4]); ac[5] = ffma2(d2, e.y, ac[5]);
            ac[6] = ffma2(d3, e.x, ac[6]); ac[7] = ffma2(d3, e.y, ac[7]);
        }
        #pragma unroll
        for (int gg = 0; gg < GRPB; gg++) {
            float2 lo = unpk(ac[2 * gg]), hi = unpk(ac[2 * gg + 1]);
            *(float4*)&sm->part[seg][gg][cg * 4] = make_float4(lo.x, lo.y, hi.x, hi.y);
        }
    }
    __syncthreads();

    if (t < 256) {
        float s = 0.f;
        #pragma unroll
        for (int r = 0; r < RANKS; r++)
            s += (sm->part[4 * r][g][col]     + sm->part[4 * r + 1][g][col])
               + (sm->part[4 * r + 2][g][col] + sm->part[4 * r + 3][g][col]);
        float m_next = sm->pmail[grp][par][0][g];
        #pragma unroll
        for (int r = 1; r < RANKS; r++) m_next = fmaxf(m_next, sm->pmail[grp][par][r][g]);
        float anew = m_used + __logf(s) + e_reg;
        if (sm->act[grp][i][g]) a = anew;
        m_used = m_next;
        sm->stage[grp][col][g] = __expf(a - m_next);
        float m = a;
        #pragma unroll
        for (int o = 16; o; o >>= 1) m = fmaxf(m, __shfl_xor_sync(0xffffffffu, m, o));
        if (lane == 0) sm->wred[grp][wrp] = m;
    }
    __syncthreads();
}

__global__ void __cluster_dims__(RANKS, 1, 1) __launch_bounds__(512, 1)
forward_kernel(const float* __restrict__ emit,
               const void*  __restrict__ mask,
               const float* __restrict__ trans,
               const float* __restrict__ tfs,
               const float* __restrict__ tte)
{
    extern __shared__ char smraw[];
    SM* sm = (SM*)smraw;

    const int t    = threadIdx.x;
    const int cta  = blockIdx.x;
    const int rank = cta & (RANKS - 1);
    const int cl   = cta >> 3;            // cluster id (0..7), 8 batches each

    const int g    = (t >> 6) & 3;
    const int col  = t & 63;
    const int cg_glob = rank * COLS + col;
    const int lane = t & 31;
    const int wrp  = t >> 5;
    const int cg   = t & 15;
    const int seg  = t >> 4;

    const int bA = cl * 8 + g;
    const int bB = cl * 8 + 4 + g;

    if (t == 0) {
        sm->isbyte = mask_byte_probe((const unsigned char*)mask);
        mbar_init(smem_u32(&sm->mbar[0][0]), RANKS);
        mbar_init(smem_u32(&sm->mbar[0][1]), RANKS);
        mbar_init(smem_u32(&sm->mbar[1][0]), RANKS);
        mbar_init(smem_u32(&sm->mbar[1][1]), RANKS);
    }

    // E slice = exp(trans[:, rank*64 .. +64])
    for (int idx = t; idx < CDIM * COLS; idx += 512) {
        int row = idx >> 6, c = idx & 63;
        sm->E[idx] = expf(trans[(size_t)row * CDIM + rank * COLS + c]);
    }
    __syncthreads();

    // mask flags for both groups
    const int isbyte = sm->isbyte;
    {
        int i = t;  // one i per thread (LDIM == 512 == blockDim)
        #pragma unroll
        for (int grp = 0; grp < NGRP; grp++) {
            int anyv = 0;
            #pragma unroll
            for (int gg = 0; gg < GRPB; gg++) {
                int m = get_mask2(mask, i * BDIM + cl * 8 + grp * 4 + gg, isbyte);
                sm->act[grp][i][gg] = (unsigned char)m;
                anyv |= m;
            }
            sm->anyg[grp][i] = (unsigned char)anyv;
        }
    }

    // alpha_0 for both groups + warp maxes
    float aA = 0.f, aB = 0.f, mA = 0.f, mB = 0.f;
    if (t < 256) {
        aA = emit[(size_t)bA * CDIM + cg_glob] + tfs[cg_glob];
        aB = emit[(size_t)bB * CDIM + cg_glob] + tfs[cg_glob];
        float m0 = aA, m1 = aB;
        #pragma unroll
        for (int o = 16; o; o >>= 1) {
            m0 = fmaxf(m0, __shfl_xor_sync(0xffffffffu, m0, o));
            m1 = fmaxf(m1, __shfl_xor_sync(0xffffffffu, m1, o));
        }
        if (lane == 0) { sm->wred[0][wrp] = m0; sm->wred[1][wrp] = m1; }
    }
    __syncthreads();

    // prologue: exchange alpha_0 local maxes (covers mbar-init visibility too)
    if (t < 64) {
        int dr = t >> 3, q = t & 7;
        float ml = fmaxf(sm->wred[q >> 2][2 * (q & 3)], sm->wred[q >> 2][2 * (q & 3) + 1]);
        stc_f32(mapa_rank(smem_u32(&sm->fm[0][0]), dr) + (unsigned)((rank * 8 + q) * 4), ml);
    }
    cluster_sync_();
    if (t < 256) {
        float ga = sm->fm[0][g], gb = sm->fm[0][4 + g];
        #pragma unroll
        for (int r = 1; r < RANKS; r++) {
            ga = fmaxf(ga, sm->fm[r][g]);
            gb = fmaxf(gb, sm->fm[r][4 + g]);
        }
        mA = ga; mB = gb;
        sm->stage[0][col][g] = __expf(aA - mA);
        sm->stage[1][col][g] = __expf(aB - mB);
    }
    __syncthreads();

    // push targets: warp wrp ships to rank wrp
    unsigned p_dst = 0, m_dst = 0, b_dst = 0;
    if (wrp < 8) {
        p_dst = mapa_rank(smem_u32(&sm->pbuf[0][0][0][0]), wrp);
        m_dst = mapa_rank(smem_u32(&sm->pmail[0][0][0][0]), wrp);
        b_dst = mapa_rank(smem_u32(&sm->mbar[0][0]), wrp);
    }

    int usesA = 0, usesB = 0;
    for (int i = 1; i < LDIM; i++) {
        const int doA = sm->anyg[0][i], doB = sm->anyg[1][i];
        if (!(doA | doB)) continue;
        const int parA = usesA & 1, parB = usesB & 1;

        float eA = 0.f, eB = 0.f;
        if (t < 256) {
            if (doA) eA = emit[((size_t)i * BDIM + bA) * CDIM + cg_glob];
            if (doB) eB = emit[((size_t)i * BDIM + bB) * CDIM + cg_glob];
            if (doA) {
                const float4* s4 = (const float4*)&sm->stage[0][0][0];
                float4 v0 = s4[lane * 2], v1 = s4[lane * 2 + 1];
                unsigned off = (unsigned)((parA * CDIM + rank * COLS) * GRPB * 4);
                stc_v4(p_dst + off + (unsigned)(lane * 32),      v0);
                stc_v4(p_dst + off + (unsigned)(lane * 32 + 16), v1);
                if (lane == 0) {
                    float4 mv = make_float4(fmaxf(sm->wred[0][0], sm->wred[0][1]),
                                            fmaxf(sm->wred[0][2], sm->wred[0][3]),
                                            fmaxf(sm->wred[0][4], sm->wred[0][5]),
                                            fmaxf(sm->wred[0][6], sm->wred[0][7]));
                    stc_v4(m_dst + (unsigned)((parA * RANKS + rank) * 16), mv);
                }
            }
            if (doB) {
                const float4* s4 = (const float4*)&sm->stage[1][0][0];
                float4 v0 = s4[lane * 2], v1 = s4[lane * 2 + 1];
                unsigned off = (unsigned)(((2 + parB) * CDIM + rank * COLS) * GRPB * 4);
                stc_v4(p_dst + off + (unsigned)(lane * 32),      v0);
                stc_v4(p_dst + off + (unsigned)(lane * 32 + 16), v1);
                if (lane == 0) {
                    float4 mv = make_float4(fmaxf(sm->wred[1][0], sm->wred[1][1]),
                                            fmaxf(sm->wred[1][2], sm->wred[1][3]),
                                            fmaxf(sm->wred[1][4], sm->wred[1][5]),
                                            fmaxf(sm->wred[1][6], sm->wred[1][7]));
                    stc_v4(m_dst + (unsigned)(((2 + parB) * RANKS + rank) * 16), mv);
                }
            }
            __syncwarp();
            if (lane == 0) {
                if (doA) mbar_arrive_remote(b_dst + (unsigned)(parA * 8));
                if (doB) mbar_arrive_remote(b_dst + (unsigned)((2 + parB) * 8));
            }
        }

        if (doA) { step_group(sm, 0, parA, (usesA >> 1) & 1, i, t, g, col, lane, wrp, cg, seg, eA, aA, mA); usesA++; }
        if (doB) { step_group(sm, 1, parB, (usesB >> 1) & 1, i, t, g, col, lane, wrp, cg, seg, eB, aB, mB); usesB++; }
    }

    // ---- final: log_z for 8 batches across 8 ranks ----
    if (t < 256) {
        float vA = aA + tte[cg_glob];
        float vB = aB + tte[cg_glob];
        float m0 = vA, m1 = vB;
        #pragma unroll
        for (int o = 16; o; o >>= 1) {
            m0 = fmaxf(m0, __shfl_xor_sync(0xffffffffu, m0, o));
            m1 = fmaxf(m1, __shfl_xor_sync(0xffffffffu, m1, o));
        }
        if (lane == 0) { sm->wred[0][wrp] = m0; sm->wred[1][wrp] = m1; }
        __syncwarp();
        // need block-level maxes; barrier below
        sm->stage[0][col][g] = vA;   // stash v for after barrier
        sm->stage[1][col][g] = vB;
    }
    __syncthreads();
    if (t < 256) {
        float mlA = fmaxf(sm->wred[0][2 * g], sm->wred[0][2 * g + 1]);
        float mlB = fmaxf(sm->wred[1][2 * g], sm->wred[1][2 * g + 1]);
        float e0 = expf(sm->stage[0][col][g] - mlA);
        float e1 = expf(sm->stage[1][col][g] - mlB);
        #pragma unroll
        for (int o = 16; o; o >>= 1) {
            e0 += __shfl_xor_sync(0xffffffffu, e0, o);
            e1 += __shfl_xor_sync(0xffffffffu, e1, o);
        }
        if (lane == 0) { sm->wsum[0][wrp] = e0; sm->wsum[1][wrp] = e1; }
    }
    __syncthreads();
    if (t < 8) {
        int grp = t >> 2, g2 = t & 3;
        float ml = fmaxf(sm->wred[grp][2 * g2], sm->wred[grp][2 * g2 + 1]);
        float sl = sm->wsum[grp][2 * g2] + sm->wsum[grp][2 * g2 + 1];
        unsigned fm0 = mapa_rank(smem_u32(&sm->fm[0][0]), 0);
        unsigned fs0 = mapa_rank(smem_u32(&sm->fs[0][0]), 0);
        stc_f32(fm0 + (unsigned)((rank * 8 + t) * 4), ml);
        stc_f32(fs0 + (unsigned)((rank * 8 + t) * 4), sl);
    }
    cluster_sync_();
    if (rank == 0 && t < 8) {
        float mg = sm->fm[0][t];
        #pragma unroll
        for (int r = 1; r < RANKS; r++) mg = fmaxf(mg, sm->fm[r][t]);
        float tot = 0.f;
        #pragma unroll
        for (int r = 0; r < RANKS; r++) tot += sm->fs[r][t] * expf(sm->fm[r][t] - mg);
        g_logz[cl * 8 + t] = mg + logf(tot);
    }
}

// ---------------------------------------------------------------------------
__global__ __launch_bounds__(512) void score_kernel(
    const float* __restrict__ emit,
    const int*   __restrict__ target,
    const void*  __restrict__ mask,
    const float* __restrict__ trans,
    const float* __restrict__ tfs,
    const float* __restrict__ tte)
{
    __shared__ int s_isbyte;
    __shared__ float red[16];
    const int t = threadIdx.x, warp = t >> 5, lane = t & 31;
    if (t == 0) s_isbyte = mask_byte_probe((const unsigned char*)mask);
    __syncthreads();
    const int isbyte = s_isbyte;

    const int idx = blockIdx.x * 512 + t;
    const int i = idx >> 6;
    const int b = idx & 63;

    float contrib = 0.f;
    if (get_mask2(mask, i * BDIM + b, isbyte)) {
        int ti = target[i * BDIM + b];
        contrib = emit[((size_t)i * BDIM + b) * CDIM + ti];
        if (i > 0) {
            int tp = target[(i - 1) * BDIM + b];
            contrib += trans[(size_t)tp * CDIM + ti];
        } else {
            contrib += tfs[ti];
        }
        int nxt = (i + 1 < LDIM) ? get_mask2(mask, (i + 1) * BDIM + b, isbyte) : 0;
        if (!nxt) contrib += tte[ti];
    }
    #pragma unroll
    for (int o = 16; o; o >>= 1) contrib += __shfl_xor_sync(0xffffffffu, contrib, o);
    if (lane == 0) red[warp] = contrib;
    __syncthreads();
    if (t == 0) {
        float s = 0.f;
        #pragma unroll
        for (int w = 0; w < 16; w++) s += red[w];
        g_scorep[blockIdx.x] = s;
    }
}

// ---------------------------------------------------------------------------
__global__ void finalize_kernel(float* __restrict__ out) {
    __shared__ float red[2];
    const int t = threadIdx.x, lane = t & 31, warp = t >> 5;
    float v = (t < BDIM) ? (g_logz[t] - g_scorep[t]) : 0.f;
    #pragma unroll
    for (int o = 16; o; o >>= 1) v += __shfl_xor_sync(0xffffffffu, v, o);
    if (lane == 0) red[warp] = v;
    __syncthreads();
    if (t == 0) out[0] = (red[0] + red[1]) / (float)BDIM;
}

// ---------------------------------------------------------------------------
extern "C" void kernel_launch(void* const* d_in, const int* in_sizes, int n_in,
                              void* d_out, int out_size) {
    const float* emit   = (const float*)d_in[0];
    const int*   target = (const int*)  d_in[1];
    const void*  mask   =               d_in[2];
    const float* trans  = (const float*)d_in[3];
    const float* tfs    = (const float*)d_in[4];
    const float* tte    = (const float*)d_in[5];
    float* out = (float*)d_out;

    cudaFuncSetAttribute(forward_kernel,
                         cudaFuncAttributeMaxDynamicSharedMemorySize, (int)sizeof(SM));

    forward_kernel<<<8 * RANKS, 512, sizeof(SM)>>>(emit, mask, trans, tfs, tte);
    score_kernel<<<64, 512>>>(emit, target, mask, trans, tfs, tte);
    finalize_kernel<<<1, 64>>>(out);
}